// round 14
// baseline (speedup 1.0000x reference)
#include <cuda_runtime.h>
#include <cuda_fp16.h>
#include <cstdint>

// out[i] = x[i] + sum_j adj[i,j]*x[j],  N=16384, D=128, adj int32 in {0,1}.
//
// fp16 mma.sync.m16n8k16 path. adj low bytes are the value (upper bytes 0):
// PRMT packs two int32 -> u16x2, *0x3C00 makes fp16 {0,1}. xT fp16 [d][j]
// precomputed once (4MB, L2-resident) is the col-major B.
//
// R14: R7 structure (proven 297us: TILE_M=128, shared single-copy B, compute
// first / memory at tail) but 512 threads, warp grid 4x4 with 32x32 warp
// tiles -> 4 warps/SMSP to cover the exposed LDSM latency, without the B
// duplication that sank the 2-CTA attempt.

#define NROWS  16384
#define DCOLS  128
#define TILE_M 128
#define TILE_K 64
#define THREADS 512
#define CHUNKS (NROWS / TILE_K)                 // 256
// pad 1KB + A0,A1 (16KB) + B0,B1,B2 (16KB)
#define SMEM_DYN (1024 + 2 * 16384 + 3 * 16384)

__device__ __align__(16) __half g_xT[(size_t)DCOLS * NROWS];   // [d][j], 4 MB

// ---------------------------------------------------------------- helpers
__device__ __forceinline__ uint32_t smem_u32(const void* p) {
    uint32_t a;
    asm("{ .reg .u64 t; cvta.to.shared.u64 t, %1; cvt.u32.u64 %0, t; }" : "=r"(a) : "l"(p));
    return a;
}
__device__ __forceinline__ uint32_t sw128(uint32_t o) { return o ^ ((o >> 3) & 0x70u); }

__device__ __forceinline__ void sts128(uint32_t a, uint32_t v0, uint32_t v1, uint32_t v2, uint32_t v3) {
    asm volatile("st.shared.v4.b32 [%0], {%1,%2,%3,%4};"
                 :: "r"(a), "r"(v0), "r"(v1), "r"(v2), "r"(v3) : "memory");
}
__device__ __forceinline__ void cp_async16(uint32_t saddr, const void* gptr) {
    asm volatile("cp.async.cg.shared.global [%0], [%1], 16;"
                 :: "r"(saddr), "l"(__cvta_generic_to_global(gptr)) : "memory");
}
__device__ __forceinline__ void cp_commit() {
    asm volatile("cp.async.commit_group;" ::: "memory");
}
#define CP_WAIT(n) asm volatile("cp.async.wait_group %0;" :: "n"(n) : "memory")

__device__ __forceinline__ void ldmx4(uint32_t* r, uint32_t addr) {
    asm volatile("ldmatrix.sync.aligned.m8n8.x4.shared.b16 {%0,%1,%2,%3}, [%4];"
                 : "=r"(r[0]), "=r"(r[1]), "=r"(r[2]), "=r"(r[3]) : "r"(addr));
}
__device__ __forceinline__ void mma16816(float* d, const uint32_t* a, uint32_t b0, uint32_t b1) {
    asm volatile("mma.sync.aligned.m16n8k16.row.col.f32.f16.f16.f32 "
                 "{%0,%1,%2,%3}, {%4,%5,%6,%7}, {%8,%9}, {%0,%1,%2,%3};"
                 : "+f"(d[0]), "+f"(d[1]), "+f"(d[2]), "+f"(d[3])
                 : "r"(a[0]), "r"(a[1]), "r"(a[2]), "r"(a[3]), "r"(b0), "r"(b1));
}

// ---------------------------------------------------------------- prep: x -> fp16 transposed [d][j]
__global__ void prep_xT_kernel(const float* __restrict__ x) {
    __shared__ float tile[32][33];
    const int j0 = blockIdx.x * 32;
    const int d0 = blockIdx.y * 32;
    const int tx = threadIdx.x, ty = threadIdx.y;   // 32 x 8
#pragma unroll
    for (int k = 0; k < 32; k += 8)
        tile[ty + k][tx] = x[(size_t)(j0 + ty + k) * DCOLS + d0 + tx];
    __syncthreads();
#pragma unroll
    for (int k = 0; k < 32; k += 8)
        g_xT[(size_t)(d0 + ty + k) * NROWS + j0 + tx] = __float2half_rn(tile[tx][ty + k]);
}

// ---------------------------------------------------------------- main GEMM
__global__ void __launch_bounds__(THREADS, 1) adjmm_kernel(
    const float* __restrict__ x, const int* __restrict__ adj, float* __restrict__ out)
{
    extern __shared__ char smraw[];
    char* sm = (char*)((((uintptr_t)smraw) + 1023) & ~(uintptr_t)1023);
    const uint32_t sb = smem_u32(sm);
    const uint32_t A_BUF[2] = { sb, sb + 16384 };
    const uint32_t B_BUF[3] = { sb + 32768, sb + 49152, sb + 65536 };

    const int tid  = threadIdx.x;
    const int w    = tid >> 5;
    const int lane = tid & 31;
    const int wr   = w >> 2;          // warp row (0..3) -> m offset 32*wr
    const int wc   = w & 3;           // warp col (0..3) -> n offset 32*wc
    const int m0g  = blockIdx.x * TILE_M;

    // A staging: unit v = p*512+tid (p<2) -> row = v>>3 (128 rows),
    // col-group g2 = v&7 (8 int32 = 2 int4 at col g2*8)
    int4 ra[2][2];

    auto ldgA = [&](int c) {
#pragma unroll
        for (int p = 0; p < 2; ++p) {
            int v = p * THREADS + tid;
            int row = v >> 3, g2 = v & 7;
            const int4* g = (const int4*)(adj + (size_t)(m0g + row) * NROWS + c * TILE_K + g2 * 8);
            ra[p][0] = g[0];
            ra[p][1] = g[1];
        }
    };
    auto stsA = [&](uint32_t base) {
#pragma unroll
        for (int p = 0; p < 2; ++p) {
            int v = p * THREADS + tid;
            int row = v >> 3, g2 = v & 7;
            uint32_t c0 = __byte_perm((uint32_t)ra[p][0].x, (uint32_t)ra[p][0].y, 0x5410) * 0x3C00u;
            uint32_t c1 = __byte_perm((uint32_t)ra[p][0].z, (uint32_t)ra[p][0].w, 0x5410) * 0x3C00u;
            uint32_t c2 = __byte_perm((uint32_t)ra[p][1].x, (uint32_t)ra[p][1].y, 0x5410) * 0x3C00u;
            uint32_t c3 = __byte_perm((uint32_t)ra[p][1].z, (uint32_t)ra[p][1].w, 0x5410) * 0x3C00u;
            sts128(base + sw128((uint32_t)(row * 128 + g2 * 16)), c0, c1, c2, c3);
        }
    };
    auto cpB = [&](int c, uint32_t base) {
#pragma unroll
        for (int i = 0; i < 2; ++i) {
            int idx = i * THREADS + tid;        // 128 rows x 8 segs of 16B
            int row = idx >> 3, seg = idx & 7;
            cp_async16(base + sw128((uint32_t)(row * 128 + seg * 16)),
                       g_xT + (size_t)row * NROWS + c * TILE_K + seg * 8);
        }
        cp_commit();
    };

    float acc[2][4][4];
#pragma unroll
    for (int mf = 0; mf < 2; ++mf)
#pragma unroll
        for (int nf = 0; nf < 4; ++nf)
#pragma unroll
            for (int i = 0; i < 4; ++i) acc[mf][nf][i] = 0.0f;

    // ---- prologue: A[0] ready, ra = chunk1, B0 ready, B1 in flight
    ldgA(0);
    cpB(0, B_BUF[0]);
    cpB(1, B_BUF[1]);
    stsA(A_BUF[0]);
    ldgA(1);
    CP_WAIT(1);
    __syncthreads();

    // ---- main loop (R7 ordering: compute first, memory at tail)
    for (int c = 0; c < CHUNKS; ++c) {
        const int s = c & 1;
        const uint32_t Ab = A_BUF[s];
        const uint32_t Bb = B_BUF[c % 3];

#pragma unroll
        for (int h = 0; h < 2; ++h) {           // k halves of 32
            // B fragments: 4 n-frags, k=32 each
            uint32_t bf[4][4];
#pragma unroll
            for (int nf = 0; nf < 4; ++nf) {
                uint32_t row = (uint32_t)(wc * 32 + nf * 8 + (lane & 7));
                ldmx4(bf[nf], Bb + sw128(row * 128 + h * 64 + ((lane >> 3) << 4)));
            }
            // A fragments: 2 m-frags x 2 k-steps (k16 each)
            uint32_t af[2][2][4];
#pragma unroll
            for (int mf = 0; mf < 2; ++mf)
#pragma unroll
                for (int ksl = 0; ksl < 2; ++ksl) {
                    uint32_t row = (uint32_t)(wr * 32 + mf * 16 + (lane & 15));
                    ldmx4(af[mf][ksl],
                          Ab + sw128(row * 128 + h * 64 + ksl * 32 + ((lane >> 4) << 4)));
                }
#pragma unroll
            for (int ksl = 0; ksl < 2; ++ksl)
#pragma unroll
                for (int nf = 0; nf < 4; ++nf) {
                    mma16816(acc[0][nf], af[0][ksl], bf[nf][2 * ksl], bf[nf][2 * ksl + 1]);
                    mma16816(acc[1][nf], af[1][ksl], bf[nf][2 * ksl], bf[nf][2 * ksl + 1]);
                }
        }

        // tail: stage A(c+1), launch A(c+2)/B(c+2) global traffic
        if (c + 1 < CHUNKS) stsA(A_BUF[s ^ 1]);
        if (c + 2 < CHUNKS) {
            ldgA(c + 2);
            cpB(c + 2, B_BUF[(c + 2) % 3]);     // slot (c+2)%3 last read in chunk c-1
            CP_WAIT(1);                          // B(c+1) landed
        } else {
            CP_WAIT(0);
        }
        __syncthreads();
    }

    // ---- epilogue: out = x + acc
#pragma unroll
    for (int mf = 0; mf < 2; ++mf) {
#pragma unroll
        for (int nf = 0; nf < 4; ++nf) {
            const int m = m0g + wr * 32 + mf * 16 + (lane >> 2);
            const int n = wc * 32 + nf * 8 + (lane & 3) * 2;
            float2 xv0 = *(const float2*)(x + (size_t)m * DCOLS + n);
            float2 o0  = { acc[mf][nf][0] + xv0.x, acc[mf][nf][1] + xv0.y };
            *(float2*)(out + (size_t)m * DCOLS + n) = o0;
            float2 xv1 = *(const float2*)(x + (size_t)(m + 8) * DCOLS + n);
            float2 o1  = { acc[mf][nf][2] + xv1.x, acc[mf][nf][3] + xv1.y };
            *(float2*)(out + (size_t)(m + 8) * DCOLS + n) = o1;
        }
    }
}

// ---------------------------------------------------------------- launcher
extern "C" void kernel_launch(void* const* d_in, const int* in_sizes, int n_in,
                              void* d_out, int out_size) {
    const float* x   = (const float*)d_in[0];
    const int*   adj = (const int*)d_in[1];
    float*       out = (float*)d_out;
    (void)in_sizes; (void)n_in; (void)out_size;

    prep_xT_kernel<<<dim3(NROWS / 32, DCOLS / 32), dim3(32, 8)>>>(x);

    cudaFuncSetAttribute(adjmm_kernel, cudaFuncAttributeMaxDynamicSharedMemorySize, SMEM_DYN);
    adjmm_kernel<<<NROWS / TILE_M, THREADS, SMEM_DYN>>>(x, adj, out);
}

// round 15
// speedup vs baseline: 1.1842x; 1.1842x over previous
#include <cuda_runtime.h>
#include <cuda_fp16.h>
#include <cstdint>

// out[i] = x[i] + sum_j adj[i,j]*x[j],  N=16384, D=128, adj int32 in {0,1}.
//
// fp16 mma.sync.m16n8k16 path. adj low bytes are the value (upper bytes 0):
// PRMT packs two int32 -> u16x2, *0x3C00 makes fp16 {0,1}. xT fp16 [d][j]
// precomputed once (4MB, L2-resident) is the col-major B.
//
// R15: R7 config (256 thr, 4x2 warp grid, 32x64 warp tiles, TILE_K=64) with
// the barrier moved BETWEEN fragment-load and MMA. LDSM(c+1) then issues right
// behind MMA(c) in each warp's stream, so the MIO burst of the next chunk
// drains under the tensor burst of the current one instead of after it.

#define NROWS  16384
#define DCOLS  128
#define TILE_M 128
#define TILE_K 64
#define THREADS 256
#define CHUNKS (NROWS / TILE_K)                 // 256
#define SMEM_DYN (1024 + 2 * 16384 + 3 * 16384) // pad + A0,A1 + B0,B1,B2

__device__ __align__(16) __half g_xT[(size_t)DCOLS * NROWS];   // [d][j], 4 MB

// ---------------------------------------------------------------- helpers
__device__ __forceinline__ uint32_t smem_u32(const void* p) {
    uint32_t a;
    asm("{ .reg .u64 t; cvta.to.shared.u64 t, %1; cvt.u32.u64 %0, t; }" : "=r"(a) : "l"(p));
    return a;
}
__device__ __forceinline__ uint32_t sw128(uint32_t o) { return o ^ ((o >> 3) & 0x70u); }

__device__ __forceinline__ void sts128(uint32_t a, uint32_t v0, uint32_t v1, uint32_t v2, uint32_t v3) {
    asm volatile("st.shared.v4.b32 [%0], {%1,%2,%3,%4};"
                 :: "r"(a), "r"(v0), "r"(v1), "r"(v2), "r"(v3) : "memory");
}
__device__ __forceinline__ void cp_async16(uint32_t saddr, const void* gptr) {
    asm volatile("cp.async.cg.shared.global [%0], [%1], 16;"
                 :: "r"(saddr), "l"(__cvta_generic_to_global(gptr)) : "memory");
}
__device__ __forceinline__ void cp_commit() {
    asm volatile("cp.async.commit_group;" ::: "memory");
}
#define CP_WAIT(n) asm volatile("cp.async.wait_group %0;" :: "n"(n) : "memory")

__device__ __forceinline__ void ldmx4(uint32_t* r, uint32_t addr) {
    asm volatile("ldmatrix.sync.aligned.m8n8.x4.shared.b16 {%0,%1,%2,%3}, [%4];"
                 : "=r"(r[0]), "=r"(r[1]), "=r"(r[2]), "=r"(r[3]) : "r"(addr));
}
__device__ __forceinline__ void mma16816(float* d, const uint32_t* a, uint32_t b0, uint32_t b1) {
    asm volatile("mma.sync.aligned.m16n8k16.row.col.f32.f16.f16.f32 "
                 "{%0,%1,%2,%3}, {%4,%5,%6,%7}, {%8,%9}, {%0,%1,%2,%3};"
                 : "+f"(d[0]), "+f"(d[1]), "+f"(d[2]), "+f"(d[3])
                 : "r"(a[0]), "r"(a[1]), "r"(a[2]), "r"(a[3]), "r"(b0), "r"(b1));
}

// ---------------------------------------------------------------- prep: x -> fp16 transposed [d][j]
__global__ void prep_xT_kernel(const float* __restrict__ x) {
    __shared__ float tile[32][33];
    const int j0 = blockIdx.x * 32;
    const int d0 = blockIdx.y * 32;
    const int tx = threadIdx.x, ty = threadIdx.y;   // 32 x 8
#pragma unroll
    for (int k = 0; k < 32; k += 8)
        tile[ty + k][tx] = x[(size_t)(j0 + ty + k) * DCOLS + d0 + tx];
    __syncthreads();
#pragma unroll
    for (int k = 0; k < 32; k += 8)
        g_xT[(size_t)(d0 + ty + k) * NROWS + j0 + tx] = __float2half_rn(tile[tx][ty + k]);
}

// ---------------------------------------------------------------- main GEMM
__global__ void __launch_bounds__(THREADS, 1) adjmm_kernel(
    const float* __restrict__ x, const int* __restrict__ adj, float* __restrict__ out)
{
    extern __shared__ char smraw[];
    char* sm = (char*)((((uintptr_t)smraw) + 1023) & ~(uintptr_t)1023);
    const uint32_t sb = smem_u32(sm);
    const uint32_t A_BUF[2] = { sb, sb + 16384 };
    const uint32_t B_BUF[3] = { sb + 32768, sb + 49152, sb + 65536 };

    const int tid  = threadIdx.x;
    const int w    = tid >> 5;
    const int lane = tid & 31;
    const int wr   = w >> 1;          // warp row (0..3) -> m offset 32*wr
    const int wc   = w & 1;           // warp col (0..1) -> n offset 64*wc
    const int m0g  = blockIdx.x * TILE_M;

    // A staging: unit u = p*256+tid -> row = u>>3 (128 rows), grp = u&7
    int4 ra[4][2];

    auto ldgA = [&](int c) {
#pragma unroll
        for (int p = 0; p < 4; ++p) {
            int u = p * THREADS + tid;
            int row = u >> 3, grp = u & 7;
            const int4* g = (const int4*)(adj + (size_t)(m0g + row) * NROWS + c * TILE_K + grp * 8);
            ra[p][0] = g[0];
            ra[p][1] = g[1];
        }
    };
    auto stsA = [&](uint32_t base) {
#pragma unroll
        for (int p = 0; p < 4; ++p) {
            int u = p * THREADS + tid;
            int row = u >> 3, grp = u & 7;
            uint32_t c0 = __byte_perm((uint32_t)ra[p][0].x, (uint32_t)ra[p][0].y, 0x5410) * 0x3C00u;
            uint32_t c1 = __byte_perm((uint32_t)ra[p][0].z, (uint32_t)ra[p][0].w, 0x5410) * 0x3C00u;
            uint32_t c2 = __byte_perm((uint32_t)ra[p][1].x, (uint32_t)ra[p][1].y, 0x5410) * 0x3C00u;
            uint32_t c3 = __byte_perm((uint32_t)ra[p][1].z, (uint32_t)ra[p][1].w, 0x5410) * 0x3C00u;
            sts128(base + sw128((uint32_t)(row * 128 + grp * 16)), c0, c1, c2, c3);
        }
    };
    auto cpB = [&](int c, uint32_t base) {
#pragma unroll
        for (int i = 0; i < 4; ++i) {
            int idx = i * THREADS + tid;        // 128 rows x 8 segs of 16B
            int row = idx >> 3, seg = idx & 7;
            cp_async16(base + sw128((uint32_t)(row * 128 + seg * 16)),
                       g_xT + (size_t)row * NROWS + c * TILE_K + seg * 8);
        }
        cp_commit();
    };

    float acc[2][8][4];
#pragma unroll
    for (int mf = 0; mf < 2; ++mf)
#pragma unroll
        for (int nf = 0; nf < 8; ++nf)
#pragma unroll
            for (int i = 0; i < 4; ++i) acc[mf][nf][i] = 0.0f;

    // ---- prologue: A[0] ready, ra = chunk1, B0 ready, B1 in flight
    ldgA(0);
    cpB(0, B_BUF[0]);
    cpB(1, B_BUF[1]);
    stsA(A_BUF[0]);
    ldgA(1);
    CP_WAIT(1);
    __syncthreads();

    // ---- main loop: [LDSM frags | tail mem | barrier | MMA]
    // MMA(c) and LDSM(c+1) are adjacent in each warp's stream with no
    // dependency, so tensor and MIO bursts overlap across iterations.
    for (int c = 0; c < CHUNKS; ++c) {
        const int s = c & 1;
        const uint32_t Ab = A_BUF[s];
        const uint32_t Bb = B_BUF[c % 3];

        // A fragments: 2 m-frags x 4 k16-steps
        uint32_t af[2][4][4];
#pragma unroll
        for (int mf = 0; mf < 2; ++mf)
#pragma unroll
            for (int ks = 0; ks < 4; ++ks) {
                uint32_t row = (uint32_t)(wr * 32 + mf * 16 + (lane & 15));
                ldmx4(af[mf][ks], Ab + sw128(row * 128 + ks * 32 + ((lane >> 4) << 4)));
            }
        // B fragments: 2 k32-halves x 8 n-frags
        uint32_t bf[2][8][4];
#pragma unroll
        for (int h = 0; h < 2; ++h)
#pragma unroll
            for (int nf = 0; nf < 8; ++nf) {
                uint32_t row = (uint32_t)(wc * 64 + nf * 8 + (lane & 7));
                ldmx4(bf[h][nf], Bb + sw128(row * 128 + h * 64 + ((lane >> 3) << 4)));
            }

        // tail: stage A(c+1), launch chunk c+2 global traffic
        if (c + 1 < CHUNKS) stsA(A_BUF[s ^ 1]);
        if (c + 2 < CHUNKS) {
            ldgA(c + 2);
            cpB(c + 2, B_BUF[(c + 2) % 3]);     // slot last read in chunk c-1
            CP_WAIT(1);                          // B(c+1) landed
        } else {
            CP_WAIT(0);
        }
        __syncthreads();

        // MMA phase (fragment registers only; overlaps next chunk's LDSM)
#pragma unroll
        for (int h = 0; h < 2; ++h)
#pragma unroll
            for (int ksl = 0; ksl < 2; ++ksl) {
                const int ks = h * 2 + ksl;
#pragma unroll
                for (int nf = 0; nf < 8; ++nf) {
                    mma16816(acc[0][nf], af[0][ks], bf[h][nf][2 * ksl], bf[h][nf][2 * ksl + 1]);
                    mma16816(acc[1][nf], af[1][ks], bf[h][nf][2 * ksl], bf[h][nf][2 * ksl + 1]);
                }
            }
    }

    // ---- epilogue: out = x + acc
#pragma unroll
    for (int mf = 0; mf < 2; ++mf) {
#pragma unroll
        for (int nf = 0; nf < 8; ++nf) {
            const int m = m0g + wr * 32 + mf * 16 + (lane >> 2);
            const int n = wc * 64 + nf * 8 + (lane & 3) * 2;
            float2 xv0 = *(const float2*)(x + (size_t)m * DCOLS + n);
            float2 o0  = { acc[mf][nf][0] + xv0.x, acc[mf][nf][1] + xv0.y };
            *(float2*)(out + (size_t)m * DCOLS + n) = o0;
            float2 xv1 = *(const float2*)(x + (size_t)(m + 8) * DCOLS + n);
            float2 o1  = { acc[mf][nf][2] + xv1.x, acc[mf][nf][3] + xv1.y };
            *(float2*)(out + (size_t)(m + 8) * DCOLS + n) = o1;
        }
    }
}

// ---------------------------------------------------------------- launcher
extern "C" void kernel_launch(void* const* d_in, const int* in_sizes, int n_in,
                              void* d_out, int out_size) {
    const float* x   = (const float*)d_in[0];
    const int*   adj = (const int*)d_in[1];
    float*       out = (float*)d_out;
    (void)in_sizes; (void)n_in; (void)out_size;

    prep_xT_kernel<<<dim3(NROWS / 32, DCOLS / 32), dim3(32, 8)>>>(x);

    cudaFuncSetAttribute(adjmm_kernel, cudaFuncAttributeMaxDynamicSharedMemorySize, SMEM_DYN);
    adjmm_kernel<<<NROWS / TILE_M, THREADS, SMEM_DYN>>>(x, adj, out);
}